// round 1
// baseline (speedup 1.0000x reference)
#include <cuda_runtime.h>

// ---------------- static problem config ----------------
#define BG   64           // graphs
#define NPG  512          // nodes per graph (layer 1)
#define NN   (BG*NPG)     // 32768 nodes
#define EPG  8192         // edges per graph
#define EE   (BG*EPG)     // 524288 edges
#define LTOK 16
#define HD   256          // hidden
#define PD   128          // projection
#define KP1  256          // kept after pool 1
#define KP2  128          // kept after pool 2
#define N2   (BG*KP1)     // 16384 nodes layer 2

// ---------------- device scratch (no allocation allowed) ----------------
__device__ float g_w[EE];
__device__ float g_x[NN*HD];     // current node features (input to GCN / pooled)
__device__ float g_h[NN*HD];     // x @ W
__device__ float g_y[NN*HD];     // GCN+relu output
__device__ float g_deg[NN];
__device__ float g_dinv[NN];
__device__ float g_score[NN];    // scores, then reused for attention gates
__device__ float g_gatev[NN];    // tanh(score) per new node
__device__ int   g_cnt[NN];
__device__ int   g_rowstart[NN];
__device__ int   g_cursor[NN];
__device__ int   g_csr[EE];
__device__ int   g_nof[NN];      // new-of-old map
__device__ int   g_oldidx[NN];   // old id per new node
__device__ int   g_src1[EE];
__device__ int   g_dst1[EE];
__device__ float g_w1[EE];
__device__ float g_out[BG*HD];
__device__ float g_pn[HD];       // p / ||p||

// ---------------- tiny fills ----------------
__global__ void fill_kernel(int sel, int n) {
    int i = blockIdx.x * blockDim.x + threadIdx.x;
    if (i >= n) return;
    if (sel == 0) g_deg[i] = 1.0f;     // deg starts at 1 (self loop)
    else if (sel == 1) g_cnt[i] = 0;
    else g_nof[i] = -1;
}

// ---------------- edge weights: mean of edge_attr ----------------
__global__ void edge_w_kernel(const float* __restrict__ ea) {
    int e = blockIdx.x * blockDim.x + threadIdx.x;
    if (e < EE) g_w[e] = 0.5f * (ea[2*e] + ea[2*e+1]);
}

// ---------------- ST encoder: masked mean of token embeddings ----------------
__global__ void st_encode_kernel(const int* __restrict__ tokens,
                                 const float* __restrict__ emb) {
    int node = blockIdx.x;
    int tid  = threadIdx.x;
    __shared__ int toks[LTOK];
    if (tid < LTOK) toks[tid] = tokens[node*LTOK + tid];
    __syncthreads();
    float acc = 0.f; int cnt = 0;
    #pragma unroll
    for (int l = 0; l < LTOK; l++) {
        int t = toks[l];
        if (t != 0) { acc += emb[t*HD + tid]; cnt++; }
    }
    g_x[node*HD + tid] = acc / (float)(cnt > 0 ? cnt : 1);
}

// ---------------- normalized direction vector p/||p|| ----------------
__global__ void normp_kernel(const float* __restrict__ p) {
    __shared__ float red[HD];
    int tid = threadIdx.x;
    float v = p[tid];
    red[tid] = v*v; __syncthreads();
    for (int s = HD/2; s > 0; s >>= 1) {
        if (tid < s) red[tid] += red[tid+s];
        __syncthreads();
    }
    g_pn[tid] = v / sqrtf(red[0]);
}

// ---------------- fp32 GEMM: C[M,256] = A[M,256] @ W[256,256] ----------------
__global__ void sgemm_kernel(const float* __restrict__ W, int M) {
    const int BM = 64, BN = 64, BK = 16;
    __shared__ __align__(16) float As[BK][BM];
    __shared__ __align__(16) float Ws[BK][BN];
    int bm = blockIdx.y, bn = blockIdx.x;
    int tid = threadIdx.x;
    int tx = tid & 15, ty = tid >> 4;
    float acc[4][4] = {};
    const float* Ab = g_x + (size_t)(bm*BM) * HD;
    const float* Wb = W + bn*BN;
    for (int k0 = 0; k0 < HD; k0 += BK) {
        {   // A tile: 64 rows x 16 k, one float4 per thread
            int row = tid >> 2, c4 = tid & 3;
            float4 v = *(const float4*)(Ab + row*HD + k0 + c4*4);
            As[c4*4+0][row] = v.x; As[c4*4+1][row] = v.y;
            As[c4*4+2][row] = v.z; As[c4*4+3][row] = v.w;
        }
        {   // W tile: 16 k x 64 cols
            int row = tid >> 4, c4 = tid & 15;
            float4 v = *(const float4*)(Wb + (k0+row)*HD + c4*4);
            *(float4*)&Ws[row][c4*4] = v;
        }
        __syncthreads();
        #pragma unroll
        for (int k = 0; k < BK; k++) {
            float4 a4 = *(float4*)&As[k][ty*4];
            float4 b4 = *(float4*)&Ws[k][tx*4];
            float a[4] = {a4.x, a4.y, a4.z, a4.w};
            float b[4] = {b4.x, b4.y, b4.z, b4.w};
            #pragma unroll
            for (int i = 0; i < 4; i++)
                #pragma unroll
                for (int j = 0; j < 4; j++)
                    acc[i][j] = fmaf(a[i], b[j], acc[i][j]);
        }
        __syncthreads();
    }
    float* Cb = g_h + (size_t)(bm*BM + ty*4) * HD + bn*BN + tx*4;
    #pragma unroll
    for (int i = 0; i < 4; i++) {
        float4 v = {acc[i][0], acc[i][1], acc[i][2], acc[i][3]};
        *(float4*)(Cb + i*HD) = v;
    }
}

// ---------------- degree accumulation ----------------
__global__ void deg_add_kernel(const int* dst_ext, int internal, int ne) {
    int e = blockIdx.x * blockDim.x + threadIdx.x;
    if (e >= ne) return;
    const int* dstp = internal ? g_dst1 : dst_ext;
    const float* wp = internal ? g_w1 : g_w;
    float we = wp[e];
    if (we != 0.f) atomicAdd(&g_deg[dstp[e]], we);
}

__global__ void dinv_kernel(int n) {
    int i = blockIdx.x * blockDim.x + threadIdx.x;
    if (i < n) g_dinv[i] = rsqrtf(g_deg[i]);
}

// ---------------- CSR build (by dst, per-graph edge slabs) ----------------
__global__ void csr_count_kernel(const int* dst_ext, int internal, int ne) {
    int e = blockIdx.x * blockDim.x + threadIdx.x;
    if (e >= ne) return;
    const int* dstp = internal ? g_dst1 : dst_ext;
    const float* wp = internal ? g_w1 : g_w;
    if (wp[e] > 0.f) atomicAdd(&g_cnt[dstp[e]], 1);
}

__global__ void scan_kernel(int n_per) {   // <<<BG, n_per>>>
    __shared__ int s[512];
    int g = blockIdx.x, tid = threadIdx.x;
    int node = g*n_per + tid;
    int c = g_cnt[node];
    s[tid] = c; __syncthreads();
    for (int off = 1; off < n_per; off <<= 1) {
        int v = (tid >= off) ? s[tid-off] : 0;
        __syncthreads();
        s[tid] += v;
        __syncthreads();
    }
    int rs = g*EPG + s[tid] - c;   // exclusive prefix + graph slab base
    g_rowstart[node] = rs;
    g_cursor[node]   = rs;
}

__global__ void csr_fill_kernel(const int* dst_ext, int internal, int ne) {
    int e = blockIdx.x * blockDim.x + threadIdx.x;
    if (e >= ne) return;
    const int* dstp = internal ? g_dst1 : dst_ext;
    const float* wp = internal ? g_w1 : g_w;
    if (wp[e] > 0.f) {
        int pos = atomicAdd(&g_cursor[dstp[e]], 1);
        g_csr[pos] = e;
    }
}

// ---------------- GCN aggregate + self loop + bias + relu ----------------
__global__ void gcn_agg_kernel(const int* src_ext, int internal,
                               const float* __restrict__ b) {
    int i = blockIdx.x, tid = threadIdx.x;
    const int* srcp = internal ? g_src1 : src_ext;
    const float* wp = internal ? g_w1 : g_w;
    int rs = g_rowstart[i], c = g_cnt[i];
    float di = g_dinv[i];
    float acc = 0.f;
    for (int j = 0; j < c; j++) {
        int e = g_csr[rs + j];
        int s = srcp[e];
        float nm = g_dinv[s] * wp[e] * di;
        acc = fmaf(g_h[s*HD + tid], nm, acc);
    }
    float v = acc + g_h[i*HD + tid] * (1.0f / g_deg[i]) + b[tid];
    g_y[i*HD + tid] = fmaxf(v, 0.f);
}

// ---------------- dot with 256-vector (scores / attention gates) ----------
// mode 0: score = g_y . g_pn          -> g_score
// mode 1: gate  = g_x . wg + bg       -> g_score
__global__ void dot_kernel(int mode, const float* wg_ext, const float* bg_ext, int n) {
    int idx = blockIdx.x * blockDim.x + threadIdx.x;
    int node = idx >> 5, lane = idx & 31;
    if (node >= n) return;
    const float* x = mode ? g_x : g_y;
    const float* v = mode ? wg_ext : g_pn;
    float s = 0.f;
    #pragma unroll
    for (int k = 0; k < HD/32; k++)
        s = fmaf(x[node*HD + k*32 + lane], v[k*32 + lane], s);
    #pragma unroll
    for (int o = 16; o > 0; o >>= 1) s += __shfl_down_sync(0xffffffffu, s, o);
    if (lane == 0) g_score[node] = s + (mode ? bg_ext[0] : 0.f);
}

// ---------------- per-graph top-k (bitonic sort, desc by score) -----------
__global__ void topk_kernel(int n_per, int k) {   // <<<BG, n_per>>>
    __shared__ float sv[512];
    __shared__ int   si[512];
    int g = blockIdx.x, tid = threadIdx.x;
    sv[tid] = g_score[g*n_per + tid];
    si[tid] = tid;
    __syncthreads();
    for (int ksz = 2; ksz <= n_per; ksz <<= 1) {
        for (int j = ksz >> 1; j > 0; j >>= 1) {
            int ixj = tid ^ j;
            if (ixj > tid) {
                bool asc = ((tid & ksz) == 0);
                float v1 = sv[tid], v2 = sv[ixj];
                int   i1 = si[tid], i2 = si[ixj];
                bool b12 = (v1 > v2) || (v1 == v2 && i1 < i2); // v1 "before" v2
                if (asc != b12) {
                    sv[tid] = v2; si[tid] = i2;
                    sv[ixj] = v1; si[ixj] = i1;
                }
            }
            __syncthreads();
        }
    }
    if (tid < k) {
        int old = g*n_per + si[tid];
        int nid = g*k + tid;
        g_nof[old]    = nid;
        g_oldidx[nid] = old;
        g_gatev[nid]  = tanhf(sv[tid]);
    }
}

__global__ void pool_gather_kernel() {   // <<<n_new, 256>>>
    int nid = blockIdx.x, tid = threadIdx.x;
    int old = g_oldidx[nid];
    g_x[nid*HD + tid] = g_y[old*HD + tid] * g_gatev[nid];
}

__global__ void edge_remap_kernel(const int* __restrict__ src,
                                  const int* __restrict__ dst) {
    int e = blockIdx.x * blockDim.x + threadIdx.x;
    if (e >= EE) return;
    int ns = g_nof[src[e]], nd = g_nof[dst[e]];
    bool keep = (ns >= 0) && (nd >= 0);
    g_src1[e] = keep ? ns : 0;
    g_dst1[e] = keep ? nd : 0;
    g_w1[e]   = keep ? g_w[e] : 0.f;
}

// ---------------- global attention pool (softmax over graph nodes) --------
__global__ void attpool_kernel(int k, int accumulate) {   // <<<BG, 256>>>
    __shared__ float a[256];
    __shared__ float red[256];
    int g = blockIdx.x, tid = threadIdx.x;
    float gv = (tid < k) ? g_score[g*k + tid] : -1e30f;
    red[tid] = gv; __syncthreads();
    for (int s = 128; s > 0; s >>= 1) {
        if (tid < s) red[tid] = fmaxf(red[tid], red[tid+s]);
        __syncthreads();
    }
    float mx = red[0]; __syncthreads();
    float ex = (tid < k) ? expf(gv - mx) : 0.f;
    red[tid] = ex; __syncthreads();
    for (int s = 128; s > 0; s >>= 1) {
        if (tid < s) red[tid] += red[tid+s];
        __syncthreads();
    }
    float inv = 1.f / red[0];
    a[tid] = ex * inv; __syncthreads();
    float acc = 0.f;
    for (int i = 0; i < k; i++)
        acc = fmaf(a[i], g_x[(g*k + i)*HD + tid], acc);
    if (accumulate) g_out[g*HD + tid] += acc;
    else            g_out[g*HD + tid]  = acc;
}

// ---------------- projection head + L2 normalize + output -----------------
__global__ void head_kernel(const float* __restrict__ Wp1, const float* __restrict__ bp1,
                            const float* __restrict__ Wp2, const float* __restrict__ bp2,
                            float* __restrict__ out) {   // <<<BG, 256>>>
    __shared__ float o[HD];
    __shared__ float hs[PD];
    __shared__ float lg[PD];
    __shared__ float red[PD];
    int g = blockIdx.x, tid = threadIdx.x;
    o[tid] = g_out[g*HD + tid];
    __syncthreads();
    if (tid < PD) {
        float s = bp1[tid];
        for (int kk = 0; kk < HD; kk++) s = fmaf(o[kk], Wp1[kk*PD + tid], s);
        hs[tid] = fmaxf(s, 0.f);
    }
    __syncthreads();
    if (tid < PD) {
        float s = bp2[tid];
        for (int kk = 0; kk < PD; kk++) s = fmaf(hs[kk], Wp2[kk*PD + tid], s);
        lg[tid] = s;
        red[tid] = s * s;
    }
    __syncthreads();
    for (int s = 64; s > 0; s >>= 1) {
        if (tid < s) red[tid] += red[tid+s];
        __syncthreads();
    }
    float nrm = fmaxf(sqrtf(red[0]), 1e-12f);
    if (tid < PD) out[g*PD + tid] = lg[tid] / nrm;        // logits [B,P]
    out[BG*PD + g*HD + tid] = o[tid];                      // out    [B,H]
}

// ---------------- driver ----------------
extern "C" void kernel_launch(void* const* d_in, const int* in_sizes, int n_in,
                              void* d_out, int out_size) {
    const int*   tokens = (const int*)  d_in[0];
    const int*   src    = (const int*)  d_in[1];
    const int*   dst    = (const int*)  d_in[2];
    const float* eattr  = (const float*)d_in[3];
    const float* emb    = (const float*)d_in[4];
    const float* W0     = (const float*)d_in[5];
    const float* b0     = (const float*)d_in[6];
    const float* W1     = (const float*)d_in[7];
    const float* b1     = (const float*)d_in[8];
    const float* p0     = (const float*)d_in[9];
    const float* p1     = (const float*)d_in[10];
    const float* wg     = (const float*)d_in[11];
    const float* bg     = (const float*)d_in[12];
    const float* Wp1    = (const float*)d_in[13];
    const float* bp1    = (const float*)d_in[14];
    const float* Wp2    = (const float*)d_in[15];
    const float* bp2    = (const float*)d_in[16];
    float* out = (float*)d_out;

    const int EB = (EE + 255) / 256;

    // edge weights + node features
    edge_w_kernel<<<EB, 256>>>(eattr);
    st_encode_kernel<<<NN, 256>>>(tokens, emb);

    // ===== layer 1 =====
    sgemm_kernel<<<dim3(HD/64, NN/64), 256>>>(W0, NN);             // h = x@W0
    fill_kernel<<<(NN+255)/256, 256>>>(0, NN);                     // deg = 1
    deg_add_kernel<<<EB, 256>>>(dst, 0, EE);
    dinv_kernel<<<(NN+255)/256, 256>>>(NN);
    fill_kernel<<<(NN+255)/256, 256>>>(1, NN);                     // cnt = 0
    csr_count_kernel<<<EB, 256>>>(dst, 0, EE);
    scan_kernel<<<BG, NPG>>>(NPG);
    csr_fill_kernel<<<EB, 256>>>(dst, 0, EE);
    gcn_agg_kernel<<<NN, 256>>>(src, 0, b0);                       // y = relu(gcn)

    // pool 1
    normp_kernel<<<1, HD>>>(p0);
    dot_kernel<<<(NN*32+255)/256, 256>>>(0, nullptr, nullptr, NN); // scores
    fill_kernel<<<(NN+255)/256, 256>>>(2, NN);                     // nof = -1
    topk_kernel<<<BG, NPG>>>(NPG, KP1);
    pool_gather_kernel<<<N2, 256>>>();                             // x = gated top-k
    edge_remap_kernel<<<EB, 256>>>(src, dst);

    // attention pool 1
    dot_kernel<<<(N2*32+255)/256, 256>>>(1, wg, bg, N2);           // gates
    attpool_kernel<<<BG, 256>>>(KP1, 0);

    // ===== layer 2 =====
    sgemm_kernel<<<dim3(HD/64, N2/64), 256>>>(W1, N2);             // h = x@W1
    fill_kernel<<<(N2+255)/256, 256>>>(0, N2);                     // deg = 1
    deg_add_kernel<<<EB, 256>>>(nullptr, 1, EE);
    dinv_kernel<<<(N2+255)/256, 256>>>(N2);
    fill_kernel<<<(N2+255)/256, 256>>>(1, N2);                     // cnt = 0
    csr_count_kernel<<<EB, 256>>>(nullptr, 1, EE);
    scan_kernel<<<BG, KP1>>>(KP1);
    csr_fill_kernel<<<EB, 256>>>(nullptr, 1, EE);
    gcn_agg_kernel<<<N2, 256>>>(nullptr, 1, b1);

    // pool 2
    normp_kernel<<<1, HD>>>(p1);
    dot_kernel<<<(N2*32+255)/256, 256>>>(0, nullptr, nullptr, N2);
    topk_kernel<<<BG, KP1>>>(KP1, KP2);
    pool_gather_kernel<<<BG*KP2, 256>>>();

    // attention pool 2 (accumulate)
    dot_kernel<<<(BG*KP2*32+255)/256, 256>>>(1, wg, bg, BG*KP2);
    attpool_kernel<<<BG, 256>>>(KP2, 1);

    // head + output
    head_kernel<<<BG, 256>>>(Wp1, bp1, Wp2, bp2, out);
}

// round 3
// speedup vs baseline: 1.3316x; 1.3316x over previous
#include <cuda_runtime.h>
#include <cuda_bf16.h>
#include <cstdint>

// ---------------- static problem config ----------------
#define BG   64
#define NPG  512
#define NN   (BG*NPG)     // 32768
#define EPG  8192
#define EE   (BG*EPG)     // 524288
#define LTOK 16
#define HD   256
#define PD   128
#define KP1  256
#define KP2  128
#define N2   (BG*KP1)     // 16384

// ---------------- device scratch ----------------
__device__ float g_w[EE];
__device__ float g_x[NN*HD];
__device__ float g_h[NN*HD];
__device__ float g_y[NN*HD];
__device__ float g_deg[NN];
__device__ float g_dinv[NN];
__device__ float g_score[NN];
__device__ float g_gatev[NN];
__device__ int   g_cnt[NN];
__device__ int   g_rowstart[NN];
__device__ int   g_cursor[NN];
__device__ int   g_csr[EE];      // src node id
__device__ float g_csrw[EE];     // precomputed norm coeff
__device__ int   g_nof[NN];
__device__ int   g_oldidx[NN];
__device__ int   g_src1[EE];
__device__ int   g_dst1[EE];
__device__ float g_w1[EE];
__device__ float g_out[BG*HD];
__device__ float g_pn[2*HD];
__device__ __nv_bfloat16 g_WThi[2][HD*HD];   // W^T split-hi  [n*K+k]
__device__ __nv_bfloat16 g_WTlo[2][HD*HD];   // W^T split-lo

// ---------------- init: deg=1, cnt=0, (nof=-1) ----------------
__global__ void init_kernel(int n, int reset_nof) {
    int i = blockIdx.x * blockDim.x + threadIdx.x;
    if (i >= n) return;
    g_deg[i] = 1.0f;
    g_cnt[i] = 0;
    if (reset_nof) g_nof[i] = -1;
}

// ---------------- edge weights + deg/cnt atomics (layer 1) ----------------
__global__ void edge_prep_kernel(const float* __restrict__ ea, const int* __restrict__ dst) {
    int e = blockIdx.x * blockDim.x + threadIdx.x;
    if (e >= EE) return;
    float w = 0.5f * (ea[2*e] + ea[2*e+1]);
    g_w[e] = w;
    int d = dst[e];
    atomicAdd(&g_deg[d], w);
    atomicAdd(&g_cnt[d], 1);
}

// ---------------- ST encoder ----------------
__global__ void st_encode_kernel(const int* __restrict__ tokens,
                                 const float* __restrict__ emb) {
    int node = blockIdx.x, tid = threadIdx.x;
    __shared__ int toks[LTOK];
    if (tid < LTOK) toks[tid] = tokens[node*LTOK + tid];
    __syncthreads();
    float acc = 0.f; int cnt = 0;
    #pragma unroll
    for (int l = 0; l < LTOK; l++) {
        int t = toks[l];
        if (t != 0) { acc += emb[(size_t)t*HD + tid]; cnt++; }
    }
    g_x[(size_t)node*HD + tid] = acc / (float)(cnt > 0 ? cnt : 1);
}

// ---------------- W^T bf16 split ----------------
__global__ void wsplit_kernel(const float* __restrict__ W0, const float* __restrict__ W1) {
    int b = blockIdx.x;                 // 512 blocks
    int which = b >> 8, k = b & 255, n = threadIdx.x;
    const float* W = which ? W1 : W0;
    float v = W[k*HD + n];
    __nv_bfloat16 hi = __float2bfloat16(v);
    float lo = v - __bfloat162float(hi);
    g_WThi[which][n*HD + k] = hi;
    g_WTlo[which][n*HD + k] = __float2bfloat16(lo);
}

// ---------------- normalized p0,p1 ----------------
__global__ void normp_kernel(const float* __restrict__ p0, const float* __restrict__ p1) {
    __shared__ float red[HD];
    int which = blockIdx.x, tid = threadIdx.x;
    const float* p = which ? p1 : p0;
    float v = p[tid];
    red[tid] = v*v; __syncthreads();
    for (int s = HD/2; s > 0; s >>= 1) {
        if (tid < s) red[tid] += red[tid+s];
        __syncthreads();
    }
    g_pn[which*HD + tid] = v / sqrtf(red[0]);
}

// ================= mma.sync bf16-split GEMM: C[M,256]=A[M,256]@W =========
// CTA: 256 threads = 4x2 warps, tile 128x128, K chunks of 64.
// smem (halves): A_hi[128][72], A_lo, B_hi[128][72], B_lo   (73728 bytes)
#define ASTR 72
#define OFF_AH 0
#define OFF_AL (128*ASTR)
#define OFF_BH (2*128*ASTR)
#define OFF_BL (3*128*ASTR)
#define GEMM_SMEM (4*128*ASTR*2)

__device__ __forceinline__ void mma_bf16(float* c, const uint32_t* a,
                                         uint32_t b0, uint32_t b1) {
    asm volatile(
        "mma.sync.aligned.m16n8k16.row.col.f32.bf16.bf16.f32 "
        "{%0,%1,%2,%3},{%4,%5,%6,%7},{%8,%9},{%0,%1,%2,%3};"
        : "+f"(c[0]), "+f"(c[1]), "+f"(c[2]), "+f"(c[3])
        : "r"(a[0]), "r"(a[1]), "r"(a[2]), "r"(a[3]), "r"(b0), "r"(b1));
}

__global__ void __launch_bounds__(256, 1) gemm_mma_kernel(const float* __restrict__ A,
                                                          int which,
                                                          float* __restrict__ C) {
    extern __shared__ __align__(16) __nv_bfloat16 sm[];
    int tid = threadIdx.x;
    int bm = blockIdx.x, bn = blockIdx.y;
    int warp = tid >> 5, lane = tid & 31;
    int wm = warp >> 1, wn = warp & 1;
    int gg = lane >> 2, tt = lane & 3;

    const float* Ab = A + (size_t)(bm*128) * HD;
    const __nv_bfloat16* Bh = g_WThi[which] + (size_t)(bn*128) * HD;
    const __nv_bfloat16* Bl = g_WTlo[which] + (size_t)(bn*128) * HD;

    float acc[2][8][4];
    #pragma unroll
    for (int mt = 0; mt < 2; mt++)
        #pragma unroll
        for (int nt = 0; nt < 8; nt++)
            #pragma unroll
            for (int q = 0; q < 4; q++) acc[mt][nt][q] = 0.f;

    for (int kc = 0; kc < 4; kc++) {
        // ---- stage A chunk 128x64 fp32 -> bf16 hi/lo ----
        #pragma unroll
        for (int it = 0; it < 4; it++) {
            int u = it*256 + tid;          // 1024 units of 8 floats
            int row = u >> 3, seg = u & 7;
            const float* s = Ab + row*HD + kc*64 + seg*8;
            float4 v0 = *(const float4*)s;
            float4 v1 = *(const float4*)(s + 4);
            float vv[8] = {v0.x, v0.y, v0.z, v0.w, v1.x, v1.y, v1.z, v1.w};
            uint32_t hp[4], lp[4];
            #pragma unroll
            for (int q = 0; q < 4; q++) {
                float a = vv[2*q], b = vv[2*q+1];
                __nv_bfloat162 H = __floats2bfloat162_rn(a, b);
                float ra = a - __bfloat162float(__low2bfloat16(H));
                float rb = b - __bfloat162float(__high2bfloat16(H));
                __nv_bfloat162 L = __floats2bfloat162_rn(ra, rb);
                hp[q] = *(uint32_t*)&H;
                lp[q] = *(uint32_t*)&L;
            }
            __nv_bfloat16* dh = sm + OFF_AH + row*ASTR + seg*8;
            __nv_bfloat16* dl = sm + OFF_AL + row*ASTR + seg*8;
            #pragma unroll
            for (int q = 0; q < 4; q++) {
                *(uint32_t*)(dh + q*2) = hp[q];
                *(uint32_t*)(dl + q*2) = lp[q];
            }
        }
        // ---- stage B chunk 128x64 bf16 hi/lo (pre-split) ----
        #pragma unroll
        for (int it = 0; it < 4; it++) {
            int u = it*256 + tid;
            int row = u >> 3, seg = u & 7;
            uint4 vh = *(const uint4*)(Bh + row*HD + kc*64 + seg*8);
            uint4 vl = *(const uint4*)(Bl + row*HD + kc*64 + seg*8);
            __nv_bfloat16* dh = sm + OFF_BH + row*ASTR + seg*8;
            __nv_bfloat16* dl = sm + OFF_BL + row*ASTR + seg*8;
            *(uint2*)(dh)     = make_uint2(vh.x, vh.y);
            *(uint2*)(dh + 4) = make_uint2(vh.z, vh.w);
            *(uint2*)(dl)     = make_uint2(vl.x, vl.y);
            *(uint2*)(dl + 4) = make_uint2(vl.z, vl.w);
        }
        __syncthreads();

        #pragma unroll
        for (int ks = 0; ks < 4; ks++) {
            uint32_t ah[2][4], al[2][4];
            #pragma unroll
            for (int mt = 0; mt < 2; mt++) {
                int r0 = wm*32 + mt*16 + gg;
                const __nv_bfloat16* bh = sm + ks*16 + tt*2;
                ah[mt][0] = *(const uint32_t*)(bh + OFF_AH + r0*ASTR);
                ah[mt][1] = *(const uint32_t*)(bh + OFF_AH + (r0+8)*ASTR);
                ah[mt][2] = *(const uint32_t*)(bh + OFF_AH + r0*ASTR + 8);
                ah[mt][3] = *(const uint32_t*)(bh + OFF_AH + (r0+8)*ASTR + 8);
                al[mt][0] = *(const uint32_t*)(bh + OFF_AL + r0*ASTR);
                al[mt][1] = *(const uint32_t*)(bh + OFF_AL + (r0+8)*ASTR);
                al[mt][2] = *(const uint32_t*)(bh + OFF_AL + r0*ASTR + 8);
                al[mt][3] = *(const uint32_t*)(bh + OFF_AL + (r0+8)*ASTR + 8);
            }
            #pragma unroll
            for (int nt = 0; nt < 8; nt++) {
                int n0 = wn*64 + nt*8 + gg;
                const __nv_bfloat16* bb = sm + n0*ASTR + ks*16 + tt*2;
                uint32_t bh0 = *(const uint32_t*)(bb + OFF_BH);
                uint32_t bh1 = *(const uint32_t*)(bb + OFF_BH + 8);
                uint32_t bl0 = *(const uint32_t*)(bb + OFF_BL);
                uint32_t bl1 = *(const uint32_t*)(bb + OFF_BL + 8);
                #pragma unroll
                for (int mt = 0; mt < 2; mt++) {
                    mma_bf16(acc[mt][nt], ah[mt], bh0, bh1);   // hi*hi
                    mma_bf16(acc[mt][nt], al[mt], bh0, bh1);   // lo*hi
                    mma_bf16(acc[mt][nt], ah[mt], bl0, bl1);   // hi*lo
                }
            }
        }
        __syncthreads();
    }

    // ---- epilogue ----
    #pragma unroll
    for (int mt = 0; mt < 2; mt++) {
        int row = bm*128 + wm*32 + mt*16 + gg;
        #pragma unroll
        for (int nt = 0; nt < 8; nt++) {
            int col = bn*128 + wn*64 + nt*8 + tt*2;
            float2 v0 = {acc[mt][nt][0], acc[mt][nt][1]};
            float2 v1 = {acc[mt][nt][2], acc[mt][nt][3]};
            *(float2*)(C + (size_t)row*HD + col)     = v0;
            *(float2*)(C + (size_t)(row+8)*HD + col) = v1;
        }
    }
}

// ---------------- dinv ----------------
__global__ void dinv_kernel(int n) {
    int i = blockIdx.x * blockDim.x + threadIdx.x;
    if (i < n) g_dinv[i] = rsqrtf(g_deg[i]);
}

// ---------------- per-graph exclusive scan of cnt -> rowstart ----------
__global__ void scan_kernel(int n_per) {
    __shared__ int s[512];
    int g = blockIdx.x, tid = threadIdx.x;
    int node = g*n_per + tid;
    int c = g_cnt[node];
    s[tid] = c; __syncthreads();
    for (int off = 1; off < n_per; off <<= 1) {
        int v = (tid >= off) ? s[tid-off] : 0;
        __syncthreads();
        s[tid] += v;
        __syncthreads();
    }
    int rs = g*EPG + s[tid] - c;
    g_rowstart[node] = rs;
    g_cursor[node]   = rs;
}

// ---------------- CSR fill: store src + precomputed norm ----------------
__global__ void csr_fill_kernel(const int* src_ext, const int* dst_ext, int internal) {
    int e = blockIdx.x * blockDim.x + threadIdx.x;
    if (e >= EE) return;
    int s, d; float w;
    if (internal) {
        s = g_src1[e];
        if (s < 0) return;
        d = g_dst1[e]; w = g_w1[e];
    } else {
        s = src_ext[e]; d = dst_ext[e]; w = g_w[e];
    }
    int pos = atomicAdd(&g_cursor[d], 1);
    g_csr[pos]  = s;
    g_csrw[pos] = g_dinv[s] * w * g_dinv[d];
}

// ---------------- GCN aggregate + self loop + bias + relu ----------------
__global__ void gcn_agg_kernel(const float* __restrict__ b) {
    int i = blockIdx.x, tid = threadIdx.x;
    int rs = g_rowstart[i], c = g_cnt[i];
    float acc = 0.f;
    int j = 0;
    for (; j + 4 <= c; j += 4) {
        int   s0 = g_csr[rs+j],   s1 = g_csr[rs+j+1],   s2 = g_csr[rs+j+2],   s3 = g_csr[rs+j+3];
        float w0 = g_csrw[rs+j],  w1 = g_csrw[rs+j+1],  w2 = g_csrw[rs+j+2],  w3 = g_csrw[rs+j+3];
        float x0 = g_h[(size_t)s0*HD+tid], x1 = g_h[(size_t)s1*HD+tid];
        float x2 = g_h[(size_t)s2*HD+tid], x3 = g_h[(size_t)s3*HD+tid];
        acc = fmaf(x0, w0, acc); acc = fmaf(x1, w1, acc);
        acc = fmaf(x2, w2, acc); acc = fmaf(x3, w3, acc);
    }
    for (; j < c; j++) {
        int s = g_csr[rs+j];
        acc = fmaf(g_h[(size_t)s*HD+tid], g_csrw[rs+j], acc);
    }
    float v = acc + g_h[(size_t)i*HD+tid] * (1.0f / g_deg[i]) + b[tid];
    g_y[(size_t)i*HD+tid] = fmaxf(v, 0.f);
}

// ---------------- dot with 256-vector ----------------
__global__ void dot_kernel(int mode, int which, const float* wg_ext,
                           const float* bg_ext, int n) {
    int idx = blockIdx.x * blockDim.x + threadIdx.x;
    int node = idx >> 5, lane = idx & 31;
    if (node >= n) return;
    const float* x = mode ? g_x : g_y;
    const float* v = mode ? wg_ext : (g_pn + which*HD);
    float s = 0.f;
    #pragma unroll
    for (int k = 0; k < HD/32; k++)
        s = fmaf(x[(size_t)node*HD + k*32 + lane], v[k*32 + lane], s);
    #pragma unroll
    for (int o = 16; o > 0; o >>= 1) s += __shfl_down_sync(0xffffffffu, s, o);
    if (lane == 0) g_score[node] = s + (mode ? bg_ext[0] : 0.f);
}

// ---------------- per-graph top-k (bitonic, desc, stable) ----------------
__global__ void topk_kernel(int n_per, int k) {
    __shared__ float sv[512];
    __shared__ int   si[512];
    int g = blockIdx.x, tid = threadIdx.x;
    sv[tid] = g_score[g*n_per + tid];
    si[tid] = tid;
    __syncthreads();
    for (int ksz = 2; ksz <= n_per; ksz <<= 1) {
        for (int j = ksz >> 1; j > 0; j >>= 1) {
            int ixj = tid ^ j;
            if (ixj > tid) {
                bool asc = ((tid & ksz) == 0);
                float v1 = sv[tid], v2 = sv[ixj];
                int   i1 = si[tid], i2 = si[ixj];
                bool b12 = (v1 > v2) || (v1 == v2 && i1 < i2);
                if (asc != b12) {
                    sv[tid] = v2; si[tid] = i2;
                    sv[ixj] = v1; si[ixj] = i1;
                }
            }
            __syncthreads();
        }
    }
    if (tid < k) {
        int old = g*n_per + si[tid];
        int nid = g*k + tid;
        g_nof[old]    = nid;
        g_oldidx[nid] = old;
        g_gatev[nid]  = tanhf(sv[tid]);
    }
}

__global__ void pool_gather_kernel() {
    int nid = blockIdx.x, tid = threadIdx.x;
    int old = g_oldidx[nid];
    g_x[(size_t)nid*HD + tid] = g_y[(size_t)old*HD + tid] * g_gatev[nid];
}

// ---------------- edge remap + deg/cnt for layer 2 ----------------
__global__ void edge_remap_kernel(const int* __restrict__ src,
                                  const int* __restrict__ dst) {
    int e = blockIdx.x * blockDim.x + threadIdx.x;
    if (e >= EE) return;
    int ns = g_nof[src[e]], nd = g_nof[dst[e]];
    bool keep = (ns >= 0) && (nd >= 0);
    if (keep) {
        float w = g_w[e];
        g_src1[e] = ns; g_dst1[e] = nd; g_w1[e] = w;
        atomicAdd(&g_deg[nd], w);
        atomicAdd(&g_cnt[nd], 1);
    } else {
        g_src1[e] = -1; g_dst1[e] = 0; g_w1[e] = 0.f;
    }
}

// ---------------- global attention pool ----------------
__global__ void attpool_kernel(int k, int accumulate) {
    __shared__ float a[256];
    __shared__ float red[256];
    int g = blockIdx.x, tid = threadIdx.x;
    float gv = (tid < k) ? g_score[g*k + tid] : -1e30f;
    red[tid] = gv; __syncthreads();
    for (int s = 128; s > 0; s >>= 1) {
        if (tid < s) red[tid] = fmaxf(red[tid], red[tid+s]);
        __syncthreads();
    }
    float mx = red[0]; __syncthreads();
    float ex = (tid < k) ? expf(gv - mx) : 0.f;
    red[tid] = ex; __syncthreads();
    for (int s = 128; s > 0; s >>= 1) {
        if (tid < s) red[tid] += red[tid+s];
        __syncthreads();
    }
    float inv = 1.f / red[0];
    a[tid] = ex * inv; __syncthreads();
    float acc = 0.f;
    for (int i = 0; i < k; i++)
        acc = fmaf(a[i], g_x[(size_t)(g*k + i)*HD + tid], acc);
    if (accumulate) g_out[g*HD + tid] += acc;
    else            g_out[g*HD + tid]  = acc;
}

// ---------------- projection head ----------------
__global__ void head_kernel(const float* __restrict__ Wp1, const float* __restrict__ bp1,
                            const float* __restrict__ Wp2, const float* __restrict__ bp2,
                            float* __restrict__ out) {
    __shared__ float o[HD];
    __shared__ float hs[PD];
    __shared__ float lg[PD];
    __shared__ float red[PD];
    int g = blockIdx.x, tid = threadIdx.x;
    o[tid] = g_out[g*HD + tid];
    __syncthreads();
    if (tid < PD) {
        float s = bp1[tid];
        for (int kk = 0; kk < HD; kk++) s = fmaf(o[kk], Wp1[kk*PD + tid], s);
        hs[tid] = fmaxf(s, 0.f);
    }
    __syncthreads();
    if (tid < PD) {
        float s = bp2[tid];
        for (int kk = 0; kk < PD; kk++) s = fmaf(hs[kk], Wp2[kk*PD + tid], s);
        lg[tid] = s;
        red[tid] = s * s;
    }
    __syncthreads();
    for (int s = 64; s > 0; s >>= 1) {
        if (tid < s) red[tid] += red[tid+s];
        __syncthreads();
    }
    float nrm = fmaxf(sqrtf(red[0]), 1e-12f);
    if (tid < PD) out[g*PD + tid] = lg[tid] / nrm;
    out[BG*PD + g*HD + tid] = o[tid];
}

// ---------------- driver ----------------
extern "C" void kernel_launch(void* const* d_in, const int* in_sizes, int n_in,
                              void* d_out, int out_size) {
    const int*   tokens = (const int*)  d_in[0];
    const int*   src    = (const int*)  d_in[1];
    const int*   dst    = (const int*)  d_in[2];
    const float* eattr  = (const float*)d_in[3];
    const float* emb    = (const float*)d_in[4];
    const float* W0     = (const float*)d_in[5];
    const float* b0     = (const float*)d_in[6];
    const float* W1     = (const float*)d_in[7];
    const float* b1     = (const float*)d_in[8];
    const float* p0     = (const float*)d_in[9];
    const float* p1     = (const float*)d_in[10];
    const float* wg     = (const float*)d_in[11];
    const float* bg     = (const float*)d_in[12];
    const float* Wp1    = (const float*)d_in[13];
    const float* bp1    = (const float*)d_in[14];
    const float* Wp2    = (const float*)d_in[15];
    const float* bp2    = (const float*)d_in[16];
    float* out = (float*)d_out;

    cudaFuncSetAttribute(gemm_mma_kernel, cudaFuncAttributeMaxDynamicSharedMemorySize, GEMM_SMEM);

    const int EB = (EE + 255) / 256;
    float* gx_dev = nullptr; cudaGetSymbolAddress((void**)&gx_dev, g_x);
    float* gh_dev = nullptr; cudaGetSymbolAddress((void**)&gh_dev, g_h);

    // prep
    init_kernel<<<(NN+255)/256, 256>>>(NN, 1);
    wsplit_kernel<<<512, 256>>>(W0, W1);
    normp_kernel<<<2, HD>>>(p0, p1);
    st_encode_kernel<<<NN, 256>>>(tokens, emb);
    edge_prep_kernel<<<EB, 256>>>(eattr, dst);

    // ===== layer 1 =====
    gemm_mma_kernel<<<dim3(NN/128, 2), 256, GEMM_SMEM>>>(gx_dev, 0, gh_dev);
    dinv_kernel<<<(NN+255)/256, 256>>>(NN);
    scan_kernel<<<BG, NPG>>>(NPG);
    csr_fill_kernel<<<EB, 256>>>(src, dst, 0);
    gcn_agg_kernel<<<NN, 256>>>(b0);

    dot_kernel<<<(NN*32+255)/256, 256>>>(0, 0, nullptr, nullptr, NN);
    topk_kernel<<<BG, NPG>>>(NPG, KP1);
    pool_gather_kernel<<<N2, 256>>>();
    init_kernel<<<(N2+255)/256, 256>>>(N2, 0);
    edge_remap_kernel<<<EB, 256>>>(src, dst);

    dot_kernel<<<(N2*32+255)/256, 256>>>(1, 0, wg, bg, N2);
    attpool_kernel<<<BG, 256>>>(KP1, 0);

    // ===== layer 2 =====
    gemm_mma_kernel<<<dim3(N2/128, 2), 256, GEMM_SMEM>>>(gx_dev, 1, gh_dev);
    dinv_kernel<<<(N2+255)/256, 256>>>(N2);
    scan_kernel<<<BG, KP1>>>(KP1);
    csr_fill_kernel<<<EB, 256>>>(nullptr, nullptr, 1);
    gcn_agg_kernel<<<N2, 256>>>(b1);

    dot_kernel<<<(N2*32+255)/256, 256>>>(0, 1, nullptr, nullptr, N2);
    topk_kernel<<<BG, KP1>>>(KP1, KP2);
    pool_gather_kernel<<<BG*KP2, 256>>>();

    dot_kernel<<<(BG*KP2*32+255)/256, 256>>>(1, 0, wg, bg, BG*KP2);
    attpool_kernel<<<BG, 256>>>(KP2, 1);

    head_kernel<<<BG, 256>>>(Wp1, bp1, Wp2, bp2, out);
}

// round 4
// speedup vs baseline: 1.8076x; 1.3575x over previous
#include <cuda_runtime.h>
#include <cuda_bf16.h>
#include <cstdint>

// ---------------- static problem config ----------------
#define BG   64
#define NPG  512
#define NN   (BG*NPG)     // 32768
#define EPG  8192
#define EE   (BG*EPG)     // 524288
#define LTOK 16
#define HD   256
#define PD   128
#define KP1  256
#define KP2  128
#define N2   (BG*KP1)     // 16384

// ---------------- device scratch ----------------
__device__ float g_w[EE];
__device__ float g_x[NN*HD];
__device__ float g_h[NN*HD];
__device__ float g_y[NN*HD];
__device__ __nv_bfloat16 g_xhi[NN*HD];   // A operand pre-split hi
__device__ __nv_bfloat16 g_xlo[NN*HD];   // A operand pre-split lo
__device__ float g_deg[NN];
__device__ float g_dinv[NN];
__device__ float g_score[NN];
__device__ float g_gatev[NN];
__device__ int   g_cnt[NN];
__device__ int   g_rowstart[NN];
__device__ int   g_cursor[NN];
__device__ int   g_csr[EE];      // src node id
__device__ float g_csrw[EE];     // precomputed norm coeff
__device__ int   g_nof[NN];
__device__ int   g_oldidx[NN];
__device__ int   g_src1[EE];
__device__ int   g_dst1[EE];
__device__ float g_w1[EE];
__device__ float g_out[BG*HD];
__device__ float g_pn[2*HD];
__device__ __nv_bfloat16 g_WThi[2][HD*HD];   // W^T split-hi  [n*K+k]
__device__ __nv_bfloat16 g_WTlo[2][HD*HD];   // W^T split-lo

// ---------------- bf16 2-term split of a float4 ----------------
__device__ __forceinline__ void split4(float4 v, uint2& hi, uint2& lo) {
    __nv_bfloat162 h0 = __floats2bfloat162_rn(v.x, v.y);
    __nv_bfloat162 h1 = __floats2bfloat162_rn(v.z, v.w);
    float rx = v.x - __bfloat162float(__low2bfloat16(h0));
    float ry = v.y - __bfloat162float(__high2bfloat16(h0));
    float rz = v.z - __bfloat162float(__low2bfloat16(h1));
    float rw = v.w - __bfloat162float(__high2bfloat16(h1));
    __nv_bfloat162 l0 = __floats2bfloat162_rn(rx, ry);
    __nv_bfloat162 l1 = __floats2bfloat162_rn(rz, rw);
    hi = make_uint2(*(uint32_t*)&h0, *(uint32_t*)&h1);
    lo = make_uint2(*(uint32_t*)&l0, *(uint32_t*)&l1);
}

// ---------------- init: deg=1, cnt=0, (nof=-1) ----------------
__global__ void init_kernel(int n, int reset_nof) {
    int i = blockIdx.x * blockDim.x + threadIdx.x;
    if (i >= n) return;
    g_deg[i] = 1.0f;
    g_cnt[i] = 0;
    if (reset_nof) g_nof[i] = -1;
}

// ---------------- edge weights + deg/cnt atomics (layer 1) ----------------
__global__ void edge_prep_kernel(const float* __restrict__ ea, const int* __restrict__ dst) {
    int e = blockIdx.x * blockDim.x + threadIdx.x;
    if (e >= EE) return;
    float w = 0.5f * (ea[2*e] + ea[2*e+1]);
    g_w[e] = w;
    int d = dst[e];
    atomicAdd(&g_deg[d], w);
    atomicAdd(&g_cnt[d], 1);
}

// ---------------- ST encoder: 4 nodes/block, float4 lanes ----------------
__global__ void __launch_bounds__(256) st_encode_kernel(const int* __restrict__ tokens,
                                                        const float* __restrict__ emb) {
    int tid = threadIdx.x;
    int grp = tid >> 6, lane = tid & 63;
    int node = blockIdx.x * 4 + grp;
    __shared__ int toks[4*LTOK];
    if (tid < 4*LTOK) toks[tid] = tokens[blockIdx.x*4*LTOK + tid];
    __syncthreads();
    const float4* emb4 = (const float4*)emb;
    float4 acc = {0.f, 0.f, 0.f, 0.f};
    int cnt = 0;
    #pragma unroll
    for (int l = 0; l < LTOK; l++) {
        int t = toks[grp*LTOK + l];
        if (t != 0) {
            float4 v = emb4[(size_t)t*64 + lane];
            acc.x += v.x; acc.y += v.y; acc.z += v.z; acc.w += v.w;
            cnt++;
        }
    }
    float inv = 1.f / (float)(cnt > 0 ? cnt : 1);
    acc.x *= inv; acc.y *= inv; acc.z *= inv; acc.w *= inv;
    size_t o = (size_t)node*64 + lane;
    ((float4*)g_x)[o] = acc;
    uint2 hi, lo;
    split4(acc, hi, lo);
    ((uint2*)g_xhi)[o] = hi;
    ((uint2*)g_xlo)[o] = lo;
}

// ---------------- W^T bf16 split ----------------
__global__ void wsplit_kernel(const float* __restrict__ W0, const float* __restrict__ W1) {
    int b = blockIdx.x;                 // 512 blocks
    int which = b >> 8, k = b & 255, n = threadIdx.x;
    const float* W = which ? W1 : W0;
    float v = W[k*HD + n];
    __nv_bfloat16 hi = __float2bfloat16(v);
    float lo = v - __bfloat162float(hi);
    g_WThi[which][n*HD + k] = hi;
    g_WTlo[which][n*HD + k] = __float2bfloat16(lo);
}

// ---------------- normalized p0,p1 ----------------
__global__ void normp_kernel(const float* __restrict__ p0, const float* __restrict__ p1) {
    __shared__ float red[HD];
    int which = blockIdx.x, tid = threadIdx.x;
    const float* p = which ? p1 : p0;
    float v = p[tid];
    red[tid] = v*v; __syncthreads();
    for (int s = HD/2; s > 0; s >>= 1) {
        if (tid < s) red[tid] += red[tid+s];
        __syncthreads();
    }
    g_pn[which*HD + tid] = v / sqrtf(red[0]);
}

// ================= mma.sync bf16-split GEMM: C[M,256]=A[M,256]@W =========
// CTA: 256 threads = 4x2 warps, tile 128x128, K chunks of 64.
#define ASTR 72
#define OFF_AH 0
#define OFF_AL (128*ASTR)
#define OFF_BH (2*128*ASTR)
#define OFF_BL (3*128*ASTR)
#define GEMM_SMEM (4*128*ASTR*2)

__device__ __forceinline__ void mma_bf16(float* c, const uint32_t* a,
                                         uint32_t b0, uint32_t b1) {
    asm volatile(
        "mma.sync.aligned.m16n8k16.row.col.f32.bf16.bf16.f32 "
        "{%0,%1,%2,%3},{%4,%5,%6,%7},{%8,%9},{%0,%1,%2,%3};"
        : "+f"(c[0]), "+f"(c[1]), "+f"(c[2]), "+f"(c[3])
        : "r"(a[0]), "r"(a[1]), "r"(a[2]), "r"(a[3]), "r"(b0), "r"(b1));
}

__global__ void __launch_bounds__(256, 1) gemm_mma_kernel(int which,
                                                          float* __restrict__ C) {
    extern __shared__ __align__(16) __nv_bfloat16 sm[];
    int tid = threadIdx.x;
    int bm = blockIdx.x, bn = blockIdx.y;
    int warp = tid >> 5, lane = tid & 31;
    int wm = warp >> 1, wn = warp & 1;
    int gg = lane >> 2, tt = lane & 3;

    const __nv_bfloat16* Ah = g_xhi + (size_t)(bm*128) * HD;
    const __nv_bfloat16* Al = g_xlo + (size_t)(bm*128) * HD;
    const __nv_bfloat16* Bh = g_WThi[which] + (size_t)(bn*128) * HD;
    const __nv_bfloat16* Bl = g_WTlo[which] + (size_t)(bn*128) * HD;

    float acc[2][8][4];
    #pragma unroll
    for (int mt = 0; mt < 2; mt++)
        #pragma unroll
        for (int nt = 0; nt < 8; nt++)
            #pragma unroll
            for (int q = 0; q < 4; q++) acc[mt][nt][q] = 0.f;

    for (int kc = 0; kc < 4; kc++) {
        // ---- stage A and B chunks (128x64 bf16 x4 arrays), pure copies ----
        #pragma unroll
        for (int it = 0; it < 4; it++) {
            int u = it*256 + tid;          // 1024 units of 8 bf16 (16B)
            int row = u >> 3, seg = u & 7;
            size_t go = (size_t)row*HD + kc*64 + seg*8;
            int so = row*ASTR + seg*8;
            *(uint4*)(sm + OFF_AH + so) = *(const uint4*)(Ah + go);
            *(uint4*)(sm + OFF_AL + so) = *(const uint4*)(Al + go);
            *(uint4*)(sm + OFF_BH + so) = *(const uint4*)(Bh + go);
            *(uint4*)(sm + OFF_BL + so) = *(const uint4*)(Bl + go);
        }
        __syncthreads();

        #pragma unroll
        for (int ks = 0; ks < 4; ks++) {
            uint32_t ah[2][4], al[2][4];
            #pragma unroll
            for (int mt = 0; mt < 2; mt++) {
                int r0 = wm*32 + mt*16 + gg;
                const __nv_bfloat16* bh = sm + ks*16 + tt*2;
                ah[mt][0] = *(const uint32_t*)(bh + OFF_AH + r0*ASTR);
                ah[mt][1] = *(const uint32_t*)(bh + OFF_AH + (r0+8)*ASTR);
                ah[mt][2] = *(const uint32_t*)(bh + OFF_AH + r0*ASTR + 8);
                ah[mt][3] = *(const uint32_t*)(bh + OFF_AH + (r0+8)*ASTR + 8);
                al[mt][0] = *(const uint32_t*)(bh + OFF_AL + r0*ASTR);
                al[mt][1] = *(const uint32_t*)(bh + OFF_AL + (r0+8)*ASTR);
                al[mt][2] = *(const uint32_t*)(bh + OFF_AL + r0*ASTR + 8);
                al[mt][3] = *(const uint32_t*)(bh + OFF_AL + (r0+8)*ASTR + 8);
            }
            #pragma unroll
            for (int nt = 0; nt < 8; nt++) {
                int n0 = wn*64 + nt*8 + gg;
                const __nv_bfloat16* bb = sm + n0*ASTR + ks*16 + tt*2;
                uint32_t bh0 = *(const uint32_t*)(bb + OFF_BH);
                uint32_t bh1 = *(const uint32_t*)(bb + OFF_BH + 8);
                uint32_t bl0 = *(const uint32_t*)(bb + OFF_BL);
                uint32_t bl1 = *(const uint32_t*)(bb + OFF_BL + 8);
                #pragma unroll
                for (int mt = 0; mt < 2; mt++) {
                    mma_bf16(acc[mt][nt], ah[mt], bh0, bh1);   // hi*hi
                    mma_bf16(acc[mt][nt], al[mt], bh0, bh1);   // lo*hi
                    mma_bf16(acc[mt][nt], ah[mt], bl0, bl1);   // hi*lo
                }
            }
        }
        __syncthreads();
    }

    // ---- epilogue ----
    #pragma unroll
    for (int mt = 0; mt < 2; mt++) {
        int row = bm*128 + wm*32 + mt*16 + gg;
        #pragma unroll
        for (int nt = 0; nt < 8; nt++) {
            int col = bn*128 + wn*64 + nt*8 + tt*2;
            float2 v0 = {acc[mt][nt][0], acc[mt][nt][1]};
            float2 v1 = {acc[mt][nt][2], acc[mt][nt][3]};
            *(float2*)(C + (size_t)row*HD + col)     = v0;
            *(float2*)(C + (size_t)(row+8)*HD + col) = v1;
        }
    }
}

// ---------------- dinv ----------------
__global__ void dinv_kernel(int n) {
    int i = blockIdx.x * blockDim.x + threadIdx.x;
    if (i < n) g_dinv[i] = rsqrtf(g_deg[i]);
}

// ---------------- per-graph exclusive scan of cnt -> rowstart ----------
__global__ void scan_kernel(int n_per) {
    __shared__ int s[512];
    int g = blockIdx.x, tid = threadIdx.x;
    int node = g*n_per + tid;
    int c = g_cnt[node];
    s[tid] = c; __syncthreads();
    for (int off = 1; off < n_per; off <<= 1) {
        int v = (tid >= off) ? s[tid-off] : 0;
        __syncthreads();
        s[tid] += v;
        __syncthreads();
    }
    int rs = g*EPG + s[tid] - c;
    g_rowstart[node] = rs;
    g_cursor[node]   = rs;
}

// ---------------- CSR fill: store src + precomputed norm ----------------
__global__ void csr_fill_kernel(const int* src_ext, const int* dst_ext, int internal) {
    int e = blockIdx.x * blockDim.x + threadIdx.x;
    if (e >= EE) return;
    int s, d; float w;
    if (internal) {
        s = g_src1[e];
        if (s < 0) return;
        d = g_dst1[e]; w = g_w1[e];
    } else {
        s = src_ext[e]; d = dst_ext[e]; w = g_w[e];
    }
    int pos = atomicAdd(&g_cursor[d], 1);
    g_csr[pos]  = s;
    g_csrw[pos] = g_dinv[s] * w * g_dinv[d];
}

// ---------------- GCN aggregate: 4 nodes/block, float4 lanes --------------
__global__ void __launch_bounds__(256) gcn_agg_kernel(const float* __restrict__ b) {
    int tid = threadIdx.x;
    int grp = tid >> 6, lane = tid & 63;
    int i = blockIdx.x * 4 + grp;
    int rs = g_rowstart[i], c = g_cnt[i];
    const float4* h4 = (const float4*)g_h;
    float4 acc = {0.f, 0.f, 0.f, 0.f};
    int j = 0;
    for (; j + 2 <= c; j += 2) {
        int   s0 = g_csr[rs+j],  s1 = g_csr[rs+j+1];
        float w0 = g_csrw[rs+j], w1 = g_csrw[rs+j+1];
        float4 x0 = h4[(size_t)s0*64 + lane];
        float4 x1 = h4[(size_t)s1*64 + lane];
        acc.x = fmaf(x0.x, w0, acc.x); acc.y = fmaf(x0.y, w0, acc.y);
        acc.z = fmaf(x0.z, w0, acc.z); acc.w = fmaf(x0.w, w0, acc.w);
        acc.x = fmaf(x1.x, w1, acc.x); acc.y = fmaf(x1.y, w1, acc.y);
        acc.z = fmaf(x1.z, w1, acc.z); acc.w = fmaf(x1.w, w1, acc.w);
    }
    if (j < c) {
        int   s0 = g_csr[rs+j];
        float w0 = g_csrw[rs+j];
        float4 x0 = h4[(size_t)s0*64 + lane];
        acc.x = fmaf(x0.x, w0, acc.x); acc.y = fmaf(x0.y, w0, acc.y);
        acc.z = fmaf(x0.z, w0, acc.z); acc.w = fmaf(x0.w, w0, acc.w);
    }
    float sl = 1.0f / g_deg[i];
    float4 xi = h4[(size_t)i*64 + lane];
    float4 bb = ((const float4*)b)[lane];
    float4 v;
    v.x = fmaxf(fmaf(xi.x, sl, acc.x) + bb.x, 0.f);
    v.y = fmaxf(fmaf(xi.y, sl, acc.y) + bb.y, 0.f);
    v.z = fmaxf(fmaf(xi.z, sl, acc.z) + bb.z, 0.f);
    v.w = fmaxf(fmaf(xi.w, sl, acc.w) + bb.w, 0.f);
    ((float4*)g_y)[(size_t)i*64 + lane] = v;
}

// ---------------- dot with 256-vector ----------------
__global__ void dot_kernel(int mode, int which, const float* wg_ext,
                           const float* bg_ext, int n) {
    int idx = blockIdx.x * blockDim.x + threadIdx.x;
    int node = idx >> 5, lane = idx & 31;
    if (node >= n) return;
    const float* x = mode ? g_x : g_y;
    const float* v = mode ? wg_ext : (g_pn + which*HD);
    float s = 0.f;
    #pragma unroll
    for (int k = 0; k < HD/32; k++)
        s = fmaf(x[(size_t)node*HD + k*32 + lane], v[k*32 + lane], s);
    #pragma unroll
    for (int o = 16; o > 0; o >>= 1) s += __shfl_down_sync(0xffffffffu, s, o);
    if (lane == 0) g_score[node] = s + (mode ? bg_ext[0] : 0.f);
}

// ---------------- per-graph top-k (bitonic, desc, stable) ----------------
__global__ void topk_kernel(int n_per, int k) {
    __shared__ float sv[512];
    __shared__ int   si[512];
    int g = blockIdx.x, tid = threadIdx.x;
    sv[tid] = g_score[g*n_per + tid];
    si[tid] = tid;
    __syncthreads();
    for (int ksz = 2; ksz <= n_per; ksz <<= 1) {
        for (int j = ksz >> 1; j > 0; j >>= 1) {
            int ixj = tid ^ j;
            if (ixj > tid) {
                bool asc = ((tid & ksz) == 0);
                float v1 = sv[tid], v2 = sv[ixj];
                int   i1 = si[tid], i2 = si[ixj];
                bool b12 = (v1 > v2) || (v1 == v2 && i1 < i2);
                if (asc != b12) {
                    sv[tid] = v2; si[tid] = i2;
                    sv[ixj] = v1; si[ixj] = i1;
                }
            }
            __syncthreads();
        }
    }
    if (tid < k) {
        int old = g*n_per + si[tid];
        int nid = g*k + tid;
        g_nof[old]    = nid;
        g_oldidx[nid] = old;
        g_gatev[nid]  = tanhf(sv[tid]);
    }
}

// ---------------- pooled gather: 4 nodes/block, float4 + bf16 split -------
__global__ void __launch_bounds__(256) pool_gather_kernel() {
    int tid = threadIdx.x;
    int grp = tid >> 6, lane = tid & 63;
    int nid = blockIdx.x * 4 + grp;
    int old = g_oldidx[nid];
    float gv = g_gatev[nid];
    float4 v = ((const float4*)g_y)[(size_t)old*64 + lane];
    v.x *= gv; v.y *= gv; v.z *= gv; v.w *= gv;
    size_t o = (size_t)nid*64 + lane;
    ((float4*)g_x)[o] = v;
    uint2 hi, lo;
    split4(v, hi, lo);
    ((uint2*)g_xhi)[o] = hi;
    ((uint2*)g_xlo)[o] = lo;
}

// ---------------- edge remap + deg/cnt for layer 2 ----------------
__global__ void edge_remap_kernel(const int* __restrict__ src,
                                  const int* __restrict__ dst) {
    int e = blockIdx.x * blockDim.x + threadIdx.x;
    if (e >= EE) return;
    int ns = g_nof[src[e]], nd = g_nof[dst[e]];
    bool keep = (ns >= 0) && (nd >= 0);
    if (keep) {
        float w = g_w[e];
        g_src1[e] = ns; g_dst1[e] = nd; g_w1[e] = w;
        atomicAdd(&g_deg[nd], w);
        atomicAdd(&g_cnt[nd], 1);
    } else {
        g_src1[e] = -1; g_dst1[e] = 0; g_w1[e] = 0.f;
    }
}

// ---------------- global attention pool ----------------
__global__ void attpool_kernel(int k, int accumulate) {
    __shared__ float a[256];
    __shared__ float red[256];
    int g = blockIdx.x, tid = threadIdx.x;
    float gv = (tid < k) ? g_score[g*k + tid] : -1e30f;
    red[tid] = gv; __syncthreads();
    for (int s = 128; s > 0; s >>= 1) {
        if (tid < s) red[tid] = fmaxf(red[tid], red[tid+s]);
        __syncthreads();
    }
    float mx = red[0]; __syncthreads();
    float ex = (tid < k) ? expf(gv - mx) : 0.f;
    red[tid] = ex; __syncthreads();
    for (int s = 128; s > 0; s >>= 1) {
        if (tid < s) red[tid] += red[tid+s];
        __syncthreads();
    }
    float inv = 1.f / red[0];
    a[tid] = ex * inv; __syncthreads();
    float acc = 0.f;
    for (int i = 0; i < k; i++)
        acc = fmaf(a[i], g_x[(size_t)(g*k + i)*HD + tid], acc);
    if (accumulate) g_out[g*HD + tid] += acc;
    else            g_out[g*HD + tid]  = acc;
}

// ---------------- projection head ----------------
__global__ void head_kernel(const float* __restrict__ Wp1, const float* __restrict__ bp1,
                            const float* __restrict__ Wp2, const float* __restrict__ bp2,
                            float* __restrict__ out) {
    __shared__ float o[HD];
    __shared__ float hs[PD];
    __shared__ float lg[PD];
    __shared__ float red[PD];
    int g = blockIdx.x, tid = threadIdx.x;
    o[tid] = g_out[g*HD + tid];
    __syncthreads();
    if (tid < PD) {
        float s = bp1[tid];
        for (int kk = 0; kk < HD; kk++) s = fmaf(o[kk], Wp1[kk*PD + tid], s);
        hs[tid] = fmaxf(s, 0.f);
    }
    __syncthreads();
    if (tid < PD) {
        float s = bp2[tid];
        for (int kk = 0; kk < PD; kk++) s = fmaf(hs[kk], Wp2[kk*PD + tid], s);
        lg[tid] = s;
        red[tid] = s * s;
    }
    __syncthreads();
    for (int s = 64; s > 0; s >>= 1) {
        if (tid < s) red[tid] += red[tid+s];
        __syncthreads();
    }
    float nrm = fmaxf(sqrtf(red[0]), 1e-12f);
    if (tid < PD) out[g*PD + tid] = lg[tid] / nrm;
    out[BG*PD + g*HD + tid] = o[tid];
}

// ---------------- driver ----------------
extern "C" void kernel_launch(void* const* d_in, const int* in_sizes, int n_in,
                              void* d_out, int out_size) {
    const int*   tokens = (const int*)  d_in[0];
    const int*   src    = (const int*)  d_in[1];
    const int*   dst    = (const int*)  d_in[2];
    const float* eattr  = (const float*)d_in[3];
    const float* emb    = (const float*)d_in[4];
    const float* W0     = (const float*)d_in[5];
    const float* b0     = (const float*)d_in[6];
    const float* W1     = (const float*)d_in[7];
    const float* b1     = (const float*)d_in[8];
    const float* p0     = (const float*)d_in[9];
    const float* p1     = (const float*)d_in[10];
    const float* wg     = (const float*)d_in[11];
    const float* bg     = (const float*)d_in[12];
    const float* Wp1    = (const float*)d_in[13];
    const float* bp1    = (const float*)d_in[14];
    const float* Wp2    = (const float*)d_in[15];
    const float* bp2    = (const float*)d_in[16];
    float* out = (float*)d_out;

    cudaFuncSetAttribute(gemm_mma_kernel, cudaFuncAttributeMaxDynamicSharedMemorySize, GEMM_SMEM);

    const int EB = (EE + 255) / 256;
    float* gh_dev = nullptr; cudaGetSymbolAddress((void**)&gh_dev, g_h);

    // prep
    init_kernel<<<(NN+255)/256, 256>>>(NN, 1);
    wsplit_kernel<<<512, 256>>>(W0, W1);
    normp_kernel<<<2, HD>>>(p0, p1);
    st_encode_kernel<<<NN/4, 256>>>(tokens, emb);
    edge_prep_kernel<<<EB, 256>>>(eattr, dst);

    // ===== layer 1 =====
    gemm_mma_kernel<<<dim3(NN/128, 2), 256, GEMM_SMEM>>>(0, gh_dev);
    dinv_kernel<<<(NN+255)/256, 256>>>(NN);
    scan_kernel<<<BG, NPG>>>(NPG);
    csr_fill_kernel<<<EB, 256>>>(src, dst, 0);
    gcn_agg_kernel<<<NN/4, 256>>>(b0);

    dot_kernel<<<(NN*32+255)/256, 256>>>(0, 0, nullptr, nullptr, NN);
    topk_kernel<<<BG, NPG>>>(NPG, KP1);
    pool_gather_kernel<<<N2/4, 256>>>();
    init_kernel<<<(N2+255)/256, 256>>>(N2, 0);
    edge_remap_kernel<<<EB, 256>>>(src, dst);

    dot_kernel<<<(N2*32+255)/256, 256>>>(1, 0, wg, bg, N2);
    attpool_kernel<<<BG, 256>>>(KP1, 0);

    // ===== layer 2 =====
    gemm_mma_kernel<<<dim3(N2/128, 2), 256, GEMM_SMEM>>>(1, gh_dev);
    dinv_kernel<<<(N2+255)/256, 256>>>(N2);
    scan_kernel<<<BG, KP1>>>(KP1);
    csr_fill_kernel<<<EB, 256>>>(nullptr, nullptr, 1);
    gcn_agg_kernel<<<N2/4, 256>>>(b1);

    dot_kernel<<<(N2*32+255)/256, 256>>>(0, 1, nullptr, nullptr, N2);
    topk_kernel<<<BG, KP1>>>(KP1, KP2);
    pool_gather_kernel<<<(BG*KP2)/4, 256>>>();

    dot_kernel<<<(BG*KP2*32+255)/256, 256>>>(1, 0, wg, bg, BG*KP2);
    attpool_kernel<<<BG, 256>>>(KP2, 1);

    head_kernel<<<BG, 256>>>(Wp1, bp1, Wp2, bp2, out);
}

// round 5
// speedup vs baseline: 1.9149x; 1.0593x over previous
#include <cuda_runtime.h>
#include <cuda_bf16.h>
#include <cstdint>

// ---------------- static problem config ----------------
#define BG   64
#define NPG  512
#define NN   (BG*NPG)     // 32768
#define EPG  8192
#define EE   (BG*EPG)     // 524288
#define LTOK 16
#define HD   256
#define PD   128
#define KP1  256
#define KP2  128
#define N2   (BG*KP1)     // 16384

// ---------------- device scratch ----------------
__device__ float g_w[EE];
__device__ float g_x[NN*HD];
__device__ float g_h[NN*HD];
__device__ float g_y[NN*HD];
__device__ __nv_bfloat16 g_xhi[NN*HD];
__device__ __nv_bfloat16 g_xlo[NN*HD];
__device__ float g_deg[NN];
__device__ float g_dinv[NN];
__device__ float g_score[NN];
__device__ float g_gatev[NN];
__device__ int   g_cnt[NN];
__device__ int   g_rowstart[NN];
__device__ int   g_cursor[NN];
__device__ int   g_csr[EE];      // src node id
__device__ float g_csrw[EE];     // precomputed norm coeff
__device__ int   g_nof[NN];
__device__ int   g_oldidx[NN];
__device__ int   g_src1[EE];
__device__ int   g_dst1[EE];
__device__ float g_w1[EE];
__device__ float g_out[BG*HD];
__device__ float g_pn[2*HD];
__device__ __nv_bfloat16 g_WThi[2][HD*HD];
__device__ __nv_bfloat16 g_WTlo[2][HD*HD];

// ---------------- bf16 2-term split of a float4 ----------------
__device__ __forceinline__ void split4(float4 v, uint2& hi, uint2& lo) {
    __nv_bfloat162 h0 = __floats2bfloat162_rn(v.x, v.y);
    __nv_bfloat162 h1 = __floats2bfloat162_rn(v.z, v.w);
    float rx = v.x - __bfloat162float(__low2bfloat16(h0));
    float ry = v.y - __bfloat162float(__high2bfloat16(h0));
    float rz = v.z - __bfloat162float(__low2bfloat16(h1));
    float rw = v.w - __bfloat162float(__high2bfloat16(h1));
    __nv_bfloat162 l0 = __floats2bfloat162_rn(rx, ry);
    __nv_bfloat162 l1 = __floats2bfloat162_rn(rz, rw);
    hi = make_uint2(*(uint32_t*)&h0, *(uint32_t*)&h1);
    lo = make_uint2(*(uint32_t*)&l0, *(uint32_t*)&l1);
}

// ---------------- edge weights + deg/cnt atomics (layer 1) ----------------
__global__ void edge_prep_kernel(const float* __restrict__ ea, const int* __restrict__ dst) {
    int e = blockIdx.x * blockDim.x + threadIdx.x;
    if (e >= EE) return;
    float w = 0.5f * (ea[2*e] + ea[2*e+1]);
    g_w[e] = w;
    int d = dst[e];
    atomicAdd(&g_deg[d], w);
    atomicAdd(&g_cnt[d], 1);
}

// ---------------- ST encoder (fused: deg=1,cnt=0,nof=-1 init) -------------
__global__ void __launch_bounds__(256) st_encode_kernel(const int* __restrict__ tokens,
                                                        const float* __restrict__ emb) {
    int tid = threadIdx.x;
    int grp = tid >> 6, lane = tid & 63;
    int node = blockIdx.x * 4 + grp;
    __shared__ int toks[4*LTOK];
    if (tid < 4*LTOK) toks[tid] = tokens[blockIdx.x*4*LTOK + tid];
    if (lane == 0) {                 // fused init for this node
        g_deg[node] = 1.0f;
        g_cnt[node] = 0;
        g_nof[node] = -1;
    }
    __syncthreads();
    const float4* emb4 = (const float4*)emb;
    float4 acc = {0.f, 0.f, 0.f, 0.f};
    int cnt = 0;
    #pragma unroll
    for (int l = 0; l < LTOK; l++) {
        int t = toks[grp*LTOK + l];
        if (t != 0) {
            float4 v = emb4[(size_t)t*64 + lane];
            acc.x += v.x; acc.y += v.y; acc.z += v.z; acc.w += v.w;
            cnt++;
        }
    }
    float inv = 1.f / (float)(cnt > 0 ? cnt : 1);
    acc.x *= inv; acc.y *= inv; acc.z *= inv; acc.w *= inv;
    size_t o = (size_t)node*64 + lane;
    ((float4*)g_x)[o] = acc;
    uint2 hi, lo;
    split4(acc, hi, lo);
    ((uint2*)g_xhi)[o] = hi;
    ((uint2*)g_xlo)[o] = lo;
}

// ---------------- W^T bf16 split ----------------
__global__ void wsplit_kernel(const float* __restrict__ W0, const float* __restrict__ W1) {
    int b = blockIdx.x;
    int which = b >> 8, k = b & 255, n = threadIdx.x;
    const float* W = which ? W1 : W0;
    float v = W[k*HD + n];
    __nv_bfloat16 hi = __float2bfloat16(v);
    float lo = v - __bfloat162float(hi);
    g_WThi[which][n*HD + k] = hi;
    g_WTlo[which][n*HD + k] = __float2bfloat16(lo);
}

// ---------------- normalized p0,p1 ----------------
__global__ void normp_kernel(const float* __restrict__ p0, const float* __restrict__ p1) {
    __shared__ float red[HD];
    int which = blockIdx.x, tid = threadIdx.x;
    const float* p = which ? p1 : p0;
    float v = p[tid];
    red[tid] = v*v; __syncthreads();
    for (int s = HD/2; s > 0; s >>= 1) {
        if (tid < s) red[tid] += red[tid+s];
        __syncthreads();
    }
    g_pn[which*HD + tid] = v / sqrtf(red[0]);
}

// ================= mma.sync bf16-split GEMM =================
#define ASTR 72
#define OFF_AH 0
#define OFF_AL (128*ASTR)
#define OFF_BH (2*128*ASTR)
#define OFF_BL (3*128*ASTR)
#define GEMM_SMEM (4*128*ASTR*2)

__device__ __forceinline__ void mma_bf16(float* c, const uint32_t* a,
                                         uint32_t b0, uint32_t b1) {
    asm volatile(
        "mma.sync.aligned.m16n8k16.row.col.f32.bf16.bf16.f32 "
        "{%0,%1,%2,%3},{%4,%5,%6,%7},{%8,%9},{%0,%1,%2,%3};"
        : "+f"(c[0]), "+f"(c[1]), "+f"(c[2]), "+f"(c[3])
        : "r"(a[0]), "r"(a[1]), "r"(a[2]), "r"(a[3]), "r"(b0), "r"(b1));
}

__global__ void __launch_bounds__(256, 1) gemm_mma_kernel(int which,
                                                          float* __restrict__ C) {
    extern __shared__ __align__(16) __nv_bfloat16 sm[];
    int tid = threadIdx.x;
    int bm = blockIdx.x, bn = blockIdx.y;
    int warp = tid >> 5, lane = tid & 31;
    int wm = warp >> 1, wn = warp & 1;
    int gg = lane >> 2, tt = lane & 3;

    const __nv_bfloat16* Ah = g_xhi + (size_t)(bm*128) * HD;
    const __nv_bfloat16* Al = g_xlo + (size_t)(bm*128) * HD;
    const __nv_bfloat16* Bh = g_WThi[which] + (size_t)(bn*128) * HD;
    const __nv_bfloat16* Bl = g_WTlo[which] + (size_t)(bn*128) * HD;

    float acc[2][8][4];
    #pragma unroll
    for (int mt = 0; mt < 2; mt++)
        #pragma unroll
        for (int nt = 0; nt < 8; nt++)
            #pragma unroll
            for (int q = 0; q < 4; q++) acc[mt][nt][q] = 0.f;

    for (int kc = 0; kc < 4; kc++) {
        #pragma unroll
        for (int it = 0; it < 4; it++) {
            int u = it*256 + tid;
            int row = u >> 3, seg = u & 7;
            size_t go = (size_t)row*HD + kc*64 + seg*8;
            int so = row*ASTR + seg*8;
            *(uint4*)(sm + OFF_AH + so) = *(const uint4*)(Ah + go);
            *(uint4*)(sm + OFF_AL + so) = *(const uint4*)(Al + go);
            *(uint4*)(sm + OFF_BH + so) = *(const uint4*)(Bh + go);
            *(uint4*)(sm + OFF_BL + so) = *(const uint4*)(Bl + go);
        }
        __syncthreads();

        #pragma unroll
        for (int ks = 0; ks < 4; ks++) {
            uint32_t ah[2][4], al[2][4];
            #pragma unroll
            for (int mt = 0; mt < 2; mt++) {
                int r0 = wm*32 + mt*16 + gg;
                const __nv_bfloat16* bh = sm + ks*16 + tt*2;
                ah[mt][0] = *(const uint32_t*)(bh + OFF_AH + r0*ASTR);
                ah[mt][1] = *(const uint32_t*)(bh + OFF_AH + (r0+8)*ASTR);
                ah[mt][2] = *(const uint32_t*)(bh + OFF_AH + r0*ASTR + 8);
                ah[mt][3] = *(const uint32_t*)(bh + OFF_AH + (r0+8)*ASTR + 8);
                al[mt][0] = *(const uint32_t*)(bh + OFF_AL + r0*ASTR);
                al[mt][1] = *(const uint32_t*)(bh + OFF_AL + (r0+8)*ASTR);
                al[mt][2] = *(const uint32_t*)(bh + OFF_AL + r0*ASTR + 8);
                al[mt][3] = *(const uint32_t*)(bh + OFF_AL + (r0+8)*ASTR + 8);
            }
            #pragma unroll
            for (int nt = 0; nt < 8; nt++) {
                int n0 = wn*64 + nt*8 + gg;
                const __nv_bfloat16* bb = sm + n0*ASTR + ks*16 + tt*2;
                uint32_t bh0 = *(const uint32_t*)(bb + OFF_BH);
                uint32_t bh1 = *(const uint32_t*)(bb + OFF_BH + 8);
                uint32_t bl0 = *(const uint32_t*)(bb + OFF_BL);
                uint32_t bl1 = *(const uint32_t*)(bb + OFF_BL + 8);
                #pragma unroll
                for (int mt = 0; mt < 2; mt++) {
                    mma_bf16(acc[mt][nt], ah[mt], bh0, bh1);
                    mma_bf16(acc[mt][nt], al[mt], bh0, bh1);
                    mma_bf16(acc[mt][nt], ah[mt], bl0, bl1);
                }
            }
        }
        __syncthreads();
    }

    #pragma unroll
    for (int mt = 0; mt < 2; mt++) {
        int row = bm*128 + wm*32 + mt*16 + gg;
        #pragma unroll
        for (int nt = 0; nt < 8; nt++) {
            int col = bn*128 + wn*64 + nt*8 + tt*2;
            float2 v0 = {acc[mt][nt][0], acc[mt][nt][1]};
            float2 v1 = {acc[mt][nt][2], acc[mt][nt][3]};
            *(float2*)(C + (size_t)row*HD + col)     = v0;
            *(float2*)(C + (size_t)(row+8)*HD + col) = v1;
        }
    }
}

// ---------------- scan (fused dinv) ----------------
__global__ void scan_kernel(int n_per) {
    __shared__ int s[512];
    int g = blockIdx.x, tid = threadIdx.x;
    int node = g*n_per + tid;
    int c = g_cnt[node];
    g_dinv[node] = rsqrtf(g_deg[node]);     // fused
    s[tid] = c; __syncthreads();
    for (int off = 1; off < n_per; off <<= 1) {
        int v = (tid >= off) ? s[tid-off] : 0;
        __syncthreads();
        s[tid] += v;
        __syncthreads();
    }
    int rs = g*EPG + s[tid] - c;
    g_rowstart[node] = rs;
    g_cursor[node]   = rs;
}

// ---------------- CSR fill ----------------
__global__ void csr_fill_kernel(const int* src_ext, const int* dst_ext, int internal) {
    int e = blockIdx.x * blockDim.x + threadIdx.x;
    if (e >= EE) return;
    int s, d; float w;
    if (internal) {
        s = g_src1[e];
        if (s < 0) return;
        d = g_dst1[e]; w = g_w1[e];
    } else {
        s = src_ext[e]; d = dst_ext[e]; w = g_w[e];
    }
    int pos = atomicAdd(&g_cursor[d], 1);
    g_csr[pos]  = s;
    g_csrw[pos] = g_dinv[s] * w * g_dinv[d];
}

// ---------------- GCN aggregate + relu (fused: topk score dot) ------------
__global__ void __launch_bounds__(256) gcn_agg_kernel(const float* __restrict__ b,
                                                      int which) {
    __shared__ float sred[8];
    int tid = threadIdx.x;
    int grp = tid >> 6, lane = tid & 63, wid = tid >> 5;
    int i = blockIdx.x * 4 + grp;
    int rs = g_rowstart[i], c = g_cnt[i];
    const float4* h4 = (const float4*)g_h;
    float4 acc = {0.f, 0.f, 0.f, 0.f};
    int j = 0;
    for (; j + 4 <= c; j += 4) {
        int   s0 = g_csr[rs+j],   s1 = g_csr[rs+j+1],  s2 = g_csr[rs+j+2],  s3 = g_csr[rs+j+3];
        float w0 = g_csrw[rs+j],  w1 = g_csrw[rs+j+1], w2 = g_csrw[rs+j+2], w3 = g_csrw[rs+j+3];
        float4 x0 = h4[(size_t)s0*64 + lane];
        float4 x1 = h4[(size_t)s1*64 + lane];
        float4 x2 = h4[(size_t)s2*64 + lane];
        float4 x3 = h4[(size_t)s3*64 + lane];
        acc.x = fmaf(x0.x, w0, acc.x); acc.y = fmaf(x0.y, w0, acc.y);
        acc.z = fmaf(x0.z, w0, acc.z); acc.w = fmaf(x0.w, w0, acc.w);
        acc.x = fmaf(x1.x, w1, acc.x); acc.y = fmaf(x1.y, w1, acc.y);
        acc.z = fmaf(x1.z, w1, acc.z); acc.w = fmaf(x1.w, w1, acc.w);
        acc.x = fmaf(x2.x, w2, acc.x); acc.y = fmaf(x2.y, w2, acc.y);
        acc.z = fmaf(x2.z, w2, acc.z); acc.w = fmaf(x2.w, w2, acc.w);
        acc.x = fmaf(x3.x, w3, acc.x); acc.y = fmaf(x3.y, w3, acc.y);
        acc.z = fmaf(x3.z, w3, acc.z); acc.w = fmaf(x3.w, w3, acc.w);
    }
    for (; j < c; j++) {
        int   s0 = g_csr[rs+j];
        float w0 = g_csrw[rs+j];
        float4 x0 = h4[(size_t)s0*64 + lane];
        acc.x = fmaf(x0.x, w0, acc.x); acc.y = fmaf(x0.y, w0, acc.y);
        acc.z = fmaf(x0.z, w0, acc.z); acc.w = fmaf(x0.w, w0, acc.w);
    }
    float sl = 1.0f / g_deg[i];
    float4 xi = h4[(size_t)i*64 + lane];
    float4 bb = ((const float4*)b)[lane];
    float4 v;
    v.x = fmaxf(fmaf(xi.x, sl, acc.x) + bb.x, 0.f);
    v.y = fmaxf(fmaf(xi.y, sl, acc.y) + bb.y, 0.f);
    v.z = fmaxf(fmaf(xi.z, sl, acc.z) + bb.z, 0.f);
    v.w = fmaxf(fmaf(xi.w, sl, acc.w) + bb.w, 0.f);
    ((float4*)g_y)[(size_t)i*64 + lane] = v;
    // fused score = y . pn[which]
    float4 pn = ((const float4*)(g_pn + which*HD))[lane];
    float s = v.x*pn.x + v.y*pn.y + v.z*pn.z + v.w*pn.w;
    #pragma unroll
    for (int o = 16; o > 0; o >>= 1) s += __shfl_down_sync(0xffffffffu, s, o);
    if ((tid & 31) == 0) sred[wid] = s;
    __syncthreads();
    if (tid < 4) g_score[blockIdx.x*4 + tid] = sred[2*tid] + sred[2*tid+1];
}

// ---------------- per-graph top-k (bitonic, desc, stable) ----------------
__global__ void topk_kernel(int n_per, int k) {
    __shared__ float sv[512];
    __shared__ int   si[512];
    int g = blockIdx.x, tid = threadIdx.x;
    sv[tid] = g_score[g*n_per + tid];
    si[tid] = tid;
    __syncthreads();
    for (int ksz = 2; ksz <= n_per; ksz <<= 1) {
        for (int j = ksz >> 1; j > 0; j >>= 1) {
            int ixj = tid ^ j;
            if (ixj > tid) {
                bool asc = ((tid & ksz) == 0);
                float v1 = sv[tid], v2 = sv[ixj];
                int   i1 = si[tid], i2 = si[ixj];
                bool b12 = (v1 > v2) || (v1 == v2 && i1 < i2);
                if (asc != b12) {
                    sv[tid] = v2; si[tid] = i2;
                    sv[ixj] = v1; si[ixj] = i1;
                }
            }
            __syncthreads();
        }
    }
    if (tid < k) {
        int old = g*n_per + si[tid];
        int nid = g*k + tid;
        g_nof[old]    = nid;
        g_oldidx[nid] = old;
        g_gatev[nid]  = tanhf(sv[tid]);
    }
}

// ---------------- pooled gather (fused: gate dot + layer2 init) -----------
__global__ void __launch_bounds__(256) pool_gather_kernel(const float* __restrict__ wg,
                                                          const float* __restrict__ bg,
                                                          int do_init) {
    __shared__ float sred[8];
    int tid = threadIdx.x;
    int grp = tid >> 6, lane = tid & 63, wid = tid >> 5;
    int nid = blockIdx.x * 4 + grp;
    int old = g_oldidx[nid];
    float gv = g_gatev[nid];
    if (do_init && lane == 0) { g_deg[nid] = 1.0f; g_cnt[nid] = 0; }
    float4 v = ((const float4*)g_y)[(size_t)old*64 + lane];
    v.x *= gv; v.y *= gv; v.z *= gv; v.w *= gv;
    size_t o = (size_t)nid*64 + lane;
    ((float4*)g_x)[o] = v;
    uint2 hi, lo;
    split4(v, hi, lo);
    ((uint2*)g_xhi)[o] = hi;
    ((uint2*)g_xlo)[o] = lo;
    // fused gate = x . wg + bg
    float4 w4 = ((const float4*)wg)[lane];
    float s = v.x*w4.x + v.y*w4.y + v.z*w4.z + v.w*w4.w;
    #pragma unroll
    for (int oo = 16; oo > 0; oo >>= 1) s += __shfl_down_sync(0xffffffffu, s, oo);
    if ((tid & 31) == 0) sred[wid] = s;
    __syncthreads();
    if (tid < 4) g_score[blockIdx.x*4 + tid] = sred[2*tid] + sred[2*tid+1] + bg[0];
}

// ---------------- edge remap + deg/cnt for layer 2 ----------------
__global__ void edge_remap_kernel(const int* __restrict__ src,
                                  const int* __restrict__ dst) {
    int e = blockIdx.x * blockDim.x + threadIdx.x;
    if (e >= EE) return;
    int ns = g_nof[src[e]], nd = g_nof[dst[e]];
    bool keep = (ns >= 0) && (nd >= 0);
    if (keep) {
        float w = g_w[e];
        g_src1[e] = ns; g_dst1[e] = nd; g_w1[e] = w;
        atomicAdd(&g_deg[nd], w);
        atomicAdd(&g_cnt[nd], 1);
    } else {
        g_src1[e] = -1; g_dst1[e] = 0; g_w1[e] = 0.f;
    }
}

// ---------------- global attention pool ----------------
__global__ void attpool_kernel(int k, int accumulate) {
    __shared__ float a[256];
    __shared__ float red[256];
    int g = blockIdx.x, tid = threadIdx.x;
    float gv = (tid < k) ? g_score[g*k + tid] : -1e30f;
    red[tid] = gv; __syncthreads();
    for (int s = 128; s > 0; s >>= 1) {
        if (tid < s) red[tid] = fmaxf(red[tid], red[tid+s]);
        __syncthreads();
    }
    float mx = red[0]; __syncthreads();
    float ex = (tid < k) ? expf(gv - mx) : 0.f;
    red[tid] = ex; __syncthreads();
    for (int s = 128; s > 0; s >>= 1) {
        if (tid < s) red[tid] += red[tid+s];
        __syncthreads();
    }
    float inv = 1.f / red[0];
    a[tid] = ex * inv; __syncthreads();
    float acc = 0.f;
    for (int i = 0; i < k; i++)
        acc = fmaf(a[i], g_x[(size_t)(g*k + i)*HD + tid], acc);
    if (accumulate) g_out[g*HD + tid] += acc;
    else            g_out[g*HD + tid]  = acc;
}

// ---------------- projection head ----------------
__global__ void head_kernel(const float* __restrict__ Wp1, const float* __restrict__ bp1,
                            const float* __restrict__ Wp2, const float* __restrict__ bp2,
                            float* __restrict__ out) {
    __shared__ float o[HD];
    __shared__ float hs[PD];
    __shared__ float lg[PD];
    __shared__ float red[PD];
    int g = blockIdx.x, tid = threadIdx.x;
    o[tid] = g_out[g*HD + tid];
    __syncthreads();
    if (tid < PD) {
        float s = bp1[tid];
        for (int kk = 0; kk < HD; kk++) s = fmaf(o[kk], Wp1[kk*PD + tid], s);
        hs[tid] = fmaxf(s, 0.f);
    }
    __syncthreads();
    if (tid < PD) {
        float s = bp2[tid];
        for (int kk = 0; kk < PD; kk++) s = fmaf(hs[kk], Wp2[kk*PD + tid], s);
        lg[tid] = s;
        red[tid] = s * s;
    }
    __syncthreads();
    for (int s = 64; s > 0; s >>= 1) {
        if (tid < s) red[tid] += red[tid+s];
        __syncthreads();
    }
    float nrm = fmaxf(sqrtf(red[0]), 1e-12f);
    if (tid < PD) out[g*PD + tid] = lg[tid] / nrm;
    out[BG*PD + g*HD + tid] = o[tid];
}

// ---------------- driver ----------------
extern "C" void kernel_launch(void* const* d_in, const int* in_sizes, int n_in,
                              void* d_out, int out_size) {
    const int*   tokens = (const int*)  d_in[0];
    const int*   src    = (const int*)  d_in[1];
    const int*   dst    = (const int*)  d_in[2];
    const float* eattr  = (const float*)d_in[3];
    const float* emb    = (const float*)d_in[4];
    const float* W0     = (const float*)d_in[5];
    const float* b0     = (const float*)d_in[6];
    const float* W1     = (const float*)d_in[7];
    const float* b1     = (const float*)d_in[8];
    const float* p0     = (const float*)d_in[9];
    const float* p1     = (const float*)d_in[10];
    const float* wg     = (const float*)d_in[11];
    const float* bg     = (const float*)d_in[12];
    const float* Wp1    = (const float*)d_in[13];
    const float* bp1    = (const float*)d_in[14];
    const float* Wp2    = (const float*)d_in[15];
    const float* bp2    = (const float*)d_in[16];
    float* out = (float*)d_out;

    cudaFuncSetAttribute(gemm_mma_kernel, cudaFuncAttributeMaxDynamicSharedMemorySize, GEMM_SMEM);

    const int EB = (EE + 255) / 256;
    float* gh_dev = nullptr; cudaGetSymbolAddress((void**)&gh_dev, g_h);

    // prep
    wsplit_kernel<<<512, 256>>>(W0, W1);
    normp_kernel<<<2, HD>>>(p0, p1);
    st_encode_kernel<<<NN/4, 256>>>(tokens, emb);          // + init deg/cnt/nof
    edge_prep_kernel<<<EB, 256>>>(eattr, dst);

    // ===== layer 1 =====
    gemm_mma_kernel<<<dim3(NN/128, 2), 256, GEMM_SMEM>>>(0, gh_dev);
    scan_kernel<<<BG, NPG>>>(NPG);                          // + dinv
    csr_fill_kernel<<<EB, 256>>>(src, dst, 0);
    gcn_agg_kernel<<<NN/4, 256>>>(b0, 0);                   // + score dot

    topk_kernel<<<BG, NPG>>>(NPG, KP1);
    pool_gather_kernel<<<N2/4, 256>>>(wg, bg, 1);           // + gate dot + init
    edge_remap_kernel<<<EB, 256>>>(src, dst);
    attpool_kernel<<<BG, 256>>>(KP1, 0);

    // ===== layer 2 =====
    gemm_mma_kernel<<<dim3(N2/128, 2), 256, GEMM_SMEM>>>(1, gh_dev);
    scan_kernel<<<BG, KP1>>>(KP1);                          // + dinv
    csr_fill_kernel<<<EB, 256>>>(nullptr, nullptr, 1);
    gcn_agg_kernel<<<N2/4, 256>>>(b1, 1);                   // + score dot

    topk_kernel<<<BG, KP1>>>(KP1, KP2);
    pool_gather_kernel<<<(BG*KP2)/4, 256>>>(wg, bg, 0);     // + gate dot
    attpool_kernel<<<BG, 256>>>(KP2, 1);

    head_kernel<<<BG, 256>>>(Wp1, bp1, Wp2, bp2, out);
}